// round 6
// baseline (speedup 1.0000x reference)
#include <cuda_runtime.h>
#include <cstdint>
#include <math.h>

// Top-8 (sorted desc) along last axis of (1024,256,128) fp32 = 262144 rows.
// Thread-per-row; 8-element Batcher merge; warp-scoped cp.async 3-stage ring
// with refill issued BEFORE consumption (2 chunk-loads always in flight).

#define THREADS        128
#define WARPS          4
#define ROWS_PER_WARP  32
#define ROWS_PER_BLOCK 128
#define NCHUNK         8      // 128 cols / 16 floats per chunk
#define CHUNKW4        4      // float4s per row per chunk
#define NBUF           3
#define SROW           20     // padded stride: lane*20 mod 32 pattern -> conflict-free LDS.128

__device__ __forceinline__ void ce(float& a, float& b) {
    float hi = fmaxf(a, b);
    b = fminf(a, b);
    a = hi;
}

__device__ __forceinline__ void cp_async16(unsigned int dst, const void* src) {
    asm volatile("cp.async.cg.shared.global [%0], [%1], 16;\n" :: "r"(dst), "l"(src));
}
__device__ __forceinline__ void cp_commit() {
    asm volatile("cp.async.commit_group;\n" ::);
}
template <int N>
__device__ __forceinline__ void cp_wait() {
    asm volatile("cp.async.wait_group %0;\n" :: "n"(N));
}

__global__ __launch_bounds__(THREADS, 7) void topk8_kernel(
    const float* __restrict__ x,
    float* __restrict__ out,
    int nrows)
{
    // [buf][warp][row*SROW + col] -> 3*4*32*20*4 = 30720 B
    __shared__ float s[NBUF][WARPS][ROWS_PER_WARP * SROW];

    const int tid = threadIdx.x;
    const int w   = tid >> 5;
    const int l   = tid & 31;
    const int row0 = blockIdx.x * ROWS_PER_BLOCK + w * ROWS_PER_WARP;

    const float4* __restrict__ gx = reinterpret_cast<const float4*>(x);

    // Producer: 32 rows x 4 float4 = 128 slots / 32 lanes = 4 cp.async per lane.
    auto load_chunk = [&](int c, int b) {
        #pragma unroll
        for (int i = 0; i < 4; ++i) {
            const int idx = l + 32 * i;
            const int r   = idx >> 2;
            const int c4  = idx & 3;
            unsigned int dst = (unsigned int)__cvta_generic_to_shared(
                &s[b][w][r * SROW + c4 * 4]);
            cp_async16(dst, gx + (size_t)(row0 + r) * 32 + c * CHUNKW4 + c4);
        }
        cp_commit();
    };

    float r0 = -INFINITY, r1 = -INFINITY, r2 = -INFINITY, r3 = -INFINITY;
    float r4 = -INFINITY, r5 = -INFINITY, r6 = -INFINITY, r7 = -INFINITY;

    load_chunk(0, 0);
    load_chunk(1, 1);

    #pragma unroll
    for (int c = 0; c < NCHUNK; ++c) {
        if (c < NCHUNK - 1) cp_wait<1>(); else cp_wait<0>();
        __syncwarp();   // chunk c visible; buffer (c+2)%3 fully drained by all lanes

        // refill FIRST: keep two loads in flight while we compute
        if (c + 2 < NCHUNK)
            load_chunk(c + 2, (c + 2) % NBUF);

        const float* sr = &s[c % NBUF][w][l * SROW];

        // two 8-element merges per chunk
        #pragma unroll
        for (int g = 0; g < 2; ++g) {
            float4 qa = *reinterpret_cast<const float4*>(sr + g * 8);
            float4 qb = *reinterpret_cast<const float4*>(sr + g * 8 + 4);
            float x0 = qa.x, x1 = qa.y, x2 = qa.z, x3 = qa.w;
            float x4 = qb.x, x5 = qb.y, x6 = qb.z, x7 = qb.w;

            // sort4 desc each half (5 CE x2)
            ce(x0, x1); ce(x2, x3); ce(x0, x2); ce(x1, x3); ce(x1, x2);
            ce(x4, x5); ce(x6, x7); ce(x4, x6); ce(x5, x7); ce(x5, x6);

            // Batcher odd-even merge(4,4) -> x0..x7 sorted desc (9 CE)
            ce(x0, x4); ce(x1, x5); ce(x2, x6); ce(x3, x7);
            ce(x2, x4); ce(x3, x5);
            ce(x1, x2); ce(x3, x4); ce(x5, x6);

            // half-cleaner: top-8 of (r desc-8, x desc-8) -> bitonic r (8 max)
            r0 = fmaxf(r0, x7); r1 = fmaxf(r1, x6);
            r2 = fmaxf(r2, x5); r3 = fmaxf(r3, x4);
            r4 = fmaxf(r4, x3); r5 = fmaxf(r5, x2);
            r6 = fmaxf(r6, x1); r7 = fmaxf(r7, x0);

            // bitonic merge-8 cleanup (12 CE) -> r sorted desc
            ce(r0, r4); ce(r1, r5); ce(r2, r6); ce(r3, r7);
            ce(r0, r2); ce(r1, r3); ce(r4, r6); ce(r5, r7);
            ce(r0, r1); ce(r2, r3); ce(r4, r5); ce(r6, r7);
        }
    }

    const int myrow = row0 + l;
    if (myrow < nrows) {
        float4* po = reinterpret_cast<float4*>(out + (size_t)myrow * 8);
        po[0] = make_float4(r0, r1, r2, r3);
        po[1] = make_float4(r4, r5, r6, r7);
    }
}

extern "C" void kernel_launch(void* const* d_in, const int* in_sizes, int n_in,
                              void* d_out, int out_size)
{
    const float* x = (const float*)d_in[0];
    float* out = (float*)d_out;

    const int nrows  = in_sizes[0] / 128;                              // 262144
    const int blocks = (nrows + ROWS_PER_BLOCK - 1) / ROWS_PER_BLOCK;  // 2048

    topk8_kernel<<<blocks, THREADS>>>(x, out, nrows);
}

// round 7
// speedup vs baseline: 1.0707x; 1.0707x over previous
#include <cuda_runtime.h>
#include <cstdint>
#include <math.h>

// Top-8 (sorted desc) along last axis of (1024,256,128) fp32 = 262144 rows.
// Thread-per-row; Batcher merge per 8 elements; warp-scoped cp.async double
// buffering. R7: per-warp/per-block SKEWED chunk order (top-8 is order-
// invariant) to break the inter-warp convoy at cp.async wait boundaries.

#define THREADS        128
#define WARPS          4
#define ROWS_PER_WARP  32
#define ROWS_PER_BLOCK 128
#define NCHUNK         8      // 128 cols / 16 floats per chunk
#define CHUNKW4        4      // float4s per row per chunk
#define SROW           20     // padded stride: conflict-free LDS.128 / STS via cp.async

__device__ __forceinline__ void ce(float& a, float& b) {
    float hi = fmaxf(a, b);
    b = fminf(a, b);
    a = hi;
}

__device__ __forceinline__ void cp_async16(unsigned int dst, const void* src) {
    asm volatile("cp.async.cg.shared.global [%0], [%1], 16;\n" :: "r"(dst), "l"(src));
}
__device__ __forceinline__ void cp_commit() {
    asm volatile("cp.async.commit_group;\n" ::);
}
template <int N>
__device__ __forceinline__ void cp_wait() {
    asm volatile("cp.async.wait_group %0;\n" :: "n"(N));
}

__global__ __launch_bounds__(THREADS, 10) void topk8_kernel(
    const float* __restrict__ x,
    float* __restrict__ out,
    int nrows)
{
    // [buf][warp][row*SROW + col] -> 2*4*32*20*4 = 20480 B
    __shared__ float s[2][WARPS][ROWS_PER_WARP * SROW];

    const int tid = threadIdx.x;
    const int w   = tid >> 5;
    const int l   = tid & 31;
    const int row0 = blockIdx.x * ROWS_PER_BLOCK + w * ROWS_PER_WARP;

    // Skewed chunk start: decorrelates wait boundaries across warps & blocks.
    const int skew = (blockIdx.x * WARPS + w) & (NCHUNK - 1);

    const float4* __restrict__ gx = reinterpret_cast<const float4*>(x);

    // Producer: 32 rows x 4 float4 = 128 slots / 32 lanes = 4 cp.async/lane.
    auto load_chunk = [&](int c, int b) {
        #pragma unroll
        for (int i = 0; i < 4; ++i) {
            const int idx = l + 32 * i;
            const int r   = idx >> 2;
            const int c4  = idx & 3;
            unsigned int dst = (unsigned int)__cvta_generic_to_shared(
                &s[b][w][r * SROW + c4 * 4]);
            cp_async16(dst, gx + (size_t)(row0 + r) * 32 + c * CHUNKW4 + c4);
        }
        cp_commit();
    };

    float r0 = -INFINITY, r1 = -INFINITY, r2 = -INFINITY, r3 = -INFINITY;
    float r4 = -INFINITY, r5 = -INFINITY, r6 = -INFINITY, r7 = -INFINITY;

    load_chunk(skew, 0);
    load_chunk((skew + 1) & (NCHUNK - 1), 1);

    #pragma unroll
    for (int i = 0; i < NCHUNK; ++i) {
        if (i < NCHUNK - 1) cp_wait<1>(); else cp_wait<0>();
        __syncwarp();

        const float* sr = &s[i & 1][w][l * SROW];

        // two 8-element merges per chunk
        #pragma unroll
        for (int g = 0; g < 2; ++g) {
            float4 qa = *reinterpret_cast<const float4*>(sr + g * 8);
            float4 qb = *reinterpret_cast<const float4*>(sr + g * 8 + 4);
            float x0 = qa.x, x1 = qa.y, x2 = qa.z, x3 = qa.w;
            float x4 = qb.x, x5 = qb.y, x6 = qb.z, x7 = qb.w;

            // sort4 desc each half (5 CE x2)
            ce(x0, x1); ce(x2, x3); ce(x0, x2); ce(x1, x3); ce(x1, x2);
            ce(x4, x5); ce(x6, x7); ce(x4, x6); ce(x5, x7); ce(x5, x6);

            // Batcher odd-even merge(4,4) -> x0..x7 sorted desc (9 CE)
            ce(x0, x4); ce(x1, x5); ce(x2, x6); ce(x3, x7);
            ce(x2, x4); ce(x3, x5);
            ce(x1, x2); ce(x3, x4); ce(x5, x6);

            // half-cleaner vs sorted r (8 max) -> r bitonic
            r0 = fmaxf(r0, x7); r1 = fmaxf(r1, x6);
            r2 = fmaxf(r2, x5); r3 = fmaxf(r3, x4);
            r4 = fmaxf(r4, x3); r5 = fmaxf(r5, x2);
            r6 = fmaxf(r6, x1); r7 = fmaxf(r7, x0);

            // bitonic merge-8 cleanup (12 CE) -> r sorted desc
            ce(r0, r4); ce(r1, r5); ce(r2, r6); ce(r3, r7);
            ce(r0, r2); ce(r1, r3); ce(r4, r6); ce(r5, r7);
            ce(r0, r1); ce(r2, r3); ce(r4, r5); ce(r6, r7);
        }

        __syncwarp();                    // all lanes done reading buf (i&1)
        if (i + 2 < NCHUNK)
            load_chunk((skew + i + 2) & (NCHUNK - 1), i & 1);
    }

    const int myrow = row0 + l;
    if (myrow < nrows) {
        float4* po = reinterpret_cast<float4*>(out + (size_t)myrow * 8);
        po[0] = make_float4(r0, r1, r2, r3);
        po[1] = make_float4(r4, r5, r6, r7);
    }
}

extern "C" void kernel_launch(void* const* d_in, const int* in_sizes, int n_in,
                              void* d_out, int out_size)
{
    const float* x = (const float*)d_in[0];
    float* out = (float*)d_out;

    const int nrows  = in_sizes[0] / 128;                              // 262144
    const int blocks = (nrows + ROWS_PER_BLOCK - 1) / ROWS_PER_BLOCK;  // 2048

    topk8_kernel<<<blocks, THREADS>>>(x, out, nrows);
}